// round 16
// baseline (speedup 1.0000x reference)
#include <cuda_runtime.h>
#include <math.h>

// features: (B=16, C=256, H=64, W=64) fp32 ; out: (B, H, W) fp32
//
// FINAL (best measured 10.72us, reproduced twice): per-pixel channel
// reduction running at the warm-path LTS delivery cap (~6.25 TB/s).
//
// Design invariants (each independently verified by a failed counter-experiment):
//  - warp = one 64-channel quarter x 32 adjacent pixels -> every warp-LDG is
//    exactly one 128B line, each line read once chip-wide (R4 broke this: +14us)
//  - interleaved load/accumulate, low MLP_p1 (R9 front-batching: +6.8us via
//    cross-CTA L1tex-queue spread)
//  - __launch_bounds__(256,7): 32 regs, 7 blocks/SM -> all 1024 blocks
//    resident in ONE wave (R11 multi-wave/work-steal: +6.2us)
//  - scalar 32b loads (float2/float4 neutral-to-worse: R2/R3/R8)
// Partials combined in smem; 64 threads run the 3->16->1 MLP + sigmoid
// epilogue and store coalesced.

#define C_DIM   256
#define HW      4096
#define NPIX    65536
#define TPB     256
#define PIX_PER_BLK 64

__global__ void __launch_bounds__(TPB, 7)
fis_kernel(const float* __restrict__ f,
           const float* __restrict__ W1,   // (3,16)
           const float* __restrict__ b1,   // 16
           const float* __restrict__ W2,   // (16,1)
           const float* __restrict__ b2,   // 1
           float* __restrict__ out)
{
    __shared__ float sp[81];          // [0:48) W1, [48:64) b1, [64:80) W2, [80] b2
    __shared__ float red_s [4][PIX_PER_BLK];
    __shared__ float red_ss[4][PIX_PER_BLK];

    int tid = threadIdx.x;
    if (tid < 81) {
        float v;
        if (tid < 48)      v = W1[tid];
        else if (tid < 64) v = b1[tid - 48];
        else if (tid < 80) v = W2[tid - 64];
        else               v = b2[0];
        sp[tid] = v;
    }
    __syncthreads();

    int q = tid >> 6;                 // channel quarter [0,4)
    int i = tid & 63;                 // pixel within block
    int p = blockIdx.x * PIX_PER_BLK + i;

    int b  = p >> 12;
    int hw = p & (HW - 1);
    const float* __restrict__ src =
        f + (size_t)b * C_DIM * HW + (size_t)(q * 64) * HW + hw;

    float s = 0.f, ss = 0.f;
    #pragma unroll 16
    for (int c = 0; c < 64; ++c) {
        float v = __ldg(src + (size_t)c * HW);
        s += v;
        ss = fmaf(v, v, ss);
    }

    red_s [q][i] = s;
    red_ss[q][i] = ss;
    __syncthreads();

    if (tid < PIX_PER_BLK) {
        float sv  = red_s [0][tid] + red_s [1][tid] + red_s [2][tid] + red_s [3][tid];
        float ssv = red_ss[0][tid] + red_ss[1][tid] + red_ss[2][tid] + red_ss[3][tid];

        const float inv_c  = 1.0f / 256.0f;
        const float inv_c1 = 1.0f / 255.0f;
        float mag = sqrtf(ssv * inv_c);
        float var = (ssv - sv * sv * inv_c) * inv_c1;
        var = fmaxf(var, 0.0f);
        float sd  = sqrtf(var);

        float x0 = fminf(mag, 1.0f);
        float x1 = fminf(var, 1.0f);
        float x2 = fminf(sd,  1.0f);

        float acc = sp[80];
        #pragma unroll
        for (int o = 0; o < 16; ++o) {
            float h = sp[48 + o];
            h = fmaf(x0, sp[o],      h);
            h = fmaf(x1, sp[16 + o], h);
            h = fmaf(x2, sp[32 + o], h);
            h = fmaxf(h, 0.0f);
            acc = fmaf(h, sp[64 + o], acc);
        }
        out[blockIdx.x * PIX_PER_BLK + tid] = 1.0f / (1.0f + __expf(-acc));
    }
}

extern "C" void kernel_launch(void* const* d_in, const int* in_sizes, int n_in,
                              void* d_out, int out_size)
{
    const float* f  = (const float*)d_in[0];
    const float* W1 = (const float*)d_in[1];
    const float* b1 = (const float*)d_in[2];
    const float* W2 = (const float*)d_in[3];
    const float* b2 = (const float*)d_in[4];
    float* out = (float*)d_out;

    fis_kernel<<<NPIX / PIX_PER_BLK, TPB>>>(f, W1, b1, W2, b2, out);
}